// round 14
// baseline (speedup 1.0000x reference)
#include <cuda_runtime.h>
#include <cuda_fp16.h>
#include <math.h>
#include <stdint.h>

// Problem constants
#define BB      16
#define NCG     256
#define NATOMS  1024
#define KF      128
#define NLAYER  13
#define THREADS 256
#define NTILES  4

#define LDX     136            // padded fp16 row stride (272 B)
#define MATU32  8704           // 128*68 u32 per fp16 matrix
#define MATB    34816          // bytes per matrix

// ---- smem byte offsets (1 CTA/SM) ----
#define OFF_X     0            // 4 x 34816 = 139264
#define OFF_W     139264       // single buffer 34816
#define OFF_DV    174080       // 512*4 f32 = 8192
#define OFF_DIST  182272       // 512 f32 = 2048
#define OFF_BIAS  184320       // 128 f32 = 512
#define SMEM_TOTAL 184832

// -------- device scratch (no allocs) --------
__device__ __align__(16) uint32_t g_Whf[NLAYER * MATU32]; // fp16 [l][k][68]
__device__ float g_bias[NLAYER * KF];
__device__ float g_G[BB * KF * 3];
__device__ float g_S[BB * 3];
__device__ float g_dx[BB * NATOMS * 3];
__device__ float g_cgoff[BB * NCG * 3];

// ---------------- helpers ----------------
__device__ __forceinline__ uint32_t smem_u32(const void* p) {
    uint32_t a;
    asm("{ .reg .u64 t; cvta.to.shared.u64 t, %1; cvt.u32.u64 %0, t; }"
        : "=r"(a) : "l"(p));
    return a;
}
__device__ __forceinline__ uint32_t pack_f16x2(float e0, float e1) {
    uint32_t r;
    asm("cvt.rn.f16x2.f32 %0, %1, %2;" : "=r"(r) : "f"(e1), "f"(e0));
    return r;
}
__device__ __forceinline__ void cp_async16(uint32_t smem_addr, const void* gptr) {
    asm volatile("cp.async.cg.shared.global [%0], [%1], 16;"
                 :: "r"(smem_addr), "l"(gptr));
}
__device__ __forceinline__ void cp_async_commit() {
    asm volatile("cp.async.commit_group;");
}
template <int N>
__device__ __forceinline__ void cp_async_wait() {
    asm volatile("cp.async.wait_group %0;" :: "n"(N));
}
__device__ __forceinline__ void ldsm_x4(uint32_t* r, uint32_t addr) {
    asm volatile("ldmatrix.sync.aligned.m8n8.x4.shared.b16 {%0,%1,%2,%3}, [%4];"
                 : "=r"(r[0]), "=r"(r[1]), "=r"(r[2]), "=r"(r[3]) : "r"(addr));
}
__device__ __forceinline__ void ldsm_x4_t(uint32_t* r, uint32_t addr) {
    asm volatile("ldmatrix.sync.aligned.m8n8.x4.trans.shared.b16 {%0,%1,%2,%3}, [%4];"
                 : "=r"(r[0]), "=r"(r[1]), "=r"(r[2]), "=r"(r[3]) : "r"(addr));
}
__device__ __forceinline__ void mma_f16(float* d, const uint32_t* a, const uint32_t* b) {
    asm volatile(
        "mma.sync.aligned.m16n8k16.row.col.f32.f16.f16.f32 "
        "{%0,%1,%2,%3},{%4,%5,%6,%7},{%8,%9},{%0,%1,%2,%3};"
        : "+f"(d[0]), "+f"(d[1]), "+f"(d[2]), "+f"(d[3])
        : "r"(a[0]), "r"(a[1]), "r"(a[2]), "r"(a[3]), "r"(b[0]), "r"(b[1]));
}
// pair barrier: warps 2*wm and 2*wm+1 (DIFFERENT SMSPs), ids 1..4
__device__ __forceinline__ void pair_bar(int wm) {
    asm volatile("bar.sync %0, 64;" :: "r"(wm + 1) : "memory");
}

// ---------------- zero scratch ----------------
__global__ void zero_kernel() {
    const int n1 = BB * KF * 3, n2 = BB * 3, n3 = BB * NCG * 3;
    const int n4 = BB * NATOMS * 3;
    const int total = n1 + n2 + n3 + n4;
    for (int i = blockIdx.x * blockDim.x + threadIdx.x; i < total;
         i += gridDim.x * blockDim.x) {
        if (i < n1)                 g_G[i] = 0.f;
        else if (i < n1 + n2)       g_S[i - n1] = 0.f;
        else if (i < n1 + n2 + n3)  g_cgoff[i - n1 - n2] = 0.f;
        else                        g_dx[i - n1 - n2 - n3] = 0.f;
    }
}

// ---------------- weight select ----------------
__device__ __forceinline__ const float* layer_W(
    int d, const float* mW1, const float* mW2, const float* uW1,
    const float* uW2, const float* dW1) {
    if (d == 12) return dW1;
    const int g = d >> 2, ty = d & 3;
    const size_t o = (size_t)g * KF * KF;
    if (ty == 0) return mW1 + o;
    if (ty == 1) return mW2 + o;
    if (ty == 2) return uW1 + o;
    return uW2 + o;
}
__device__ __forceinline__ const float* layer_b(
    int d, const float* mb1, const float* mb2, const float* ub1,
    const float* ub2, const float* db1) {
    if (d == 12) return db1;
    const int g = d >> 2, ty = d & 3;
    const size_t o = (size_t)g * KF;
    if (ty == 0) return mb1 + o;
    if (ty == 1) return mb2 + o;
    if (ty == 2) return ub1 + o;
    return ub2 + o;
}

#define NWQUAD (NLAYER * KF * 32)   // 53248 col-quads

__global__ void convert_kernel(const float* mW1, const float* mb1,
                               const float* mW2, const float* mb2,
                               const float* uW1, const float* ub1,
                               const float* uW2, const float* ub2,
                               const float* dW1, const float* db1) {
    const int i = blockIdx.x * blockDim.x + threadIdx.x;
    if (i < NWQUAD) {
        const int d   = i / (KF * 32);
        const int rem = i % (KF * 32);
        const int k   = rem >> 5;
        const int cq  = rem & 31;
        const float* W = layer_W(d, mW1, mW2, uW1, uW2, dW1);
        const float4 w = *(const float4*)(W + (size_t)k * KF + 4 * cq);
        const int base = d * MATU32 + k * 68 + 2 * cq;
        g_Whf[base]     = pack_f16x2(w.x, w.y);
        g_Whf[base + 1] = pack_f16x2(w.z, w.w);
    } else if (i < NWQUAD + NLAYER * KF) {
        const int j = i - NWQUAD;
        const int d = j >> 7, c = j & 127;
        g_bias[j] = layer_b(d, mb1, mb2, ub1, ub2, db1)[c];
    }
}

// ---------------- fused MLP chain: weight-stationary registers, 4 tiles/CTA ----------------
extern __shared__ __align__(16) char smem[];

__global__ __launch_bounds__(THREADS, 1)
void fused_kernel(const float* __restrict__ cg_xyz) {
    const uint32_t sb = smem_u32(smem);
    const int t = threadIdx.x, wid = t >> 5, lane = t & 31;
    const int wm = wid >> 1;       // rows [32wm, 32wm+32); pair warps on different SMSPs
    const int wn = wid & 1;        // cols [64wn, 64wn+64)
    const int grp = lane >> 2, tig = lane & 3;
    const int r16 = lane & 15, c8 = (lane >> 4) << 3;

    const int blk = blockIdx.x;    // 0..255; tiles 4*blk..4*blk+3
    const int b   = blk >> 4;      // all 4 tiles share batch b

    float* dv    = (float*)(smem + OFF_DV);     // [512][4]
    float* dist  = (float*)(smem + OFF_DIST);   // [512]
    float* biasS = (float*)(smem + OFF_BIAS);   // [128], per-layer

    // phase 0: dv / dist for 512 rows
    for (int r = t; r < NTILES * 128; r += THREADS) {
        const int tile  = blk * 4 + (r >> 7);
        const int local = r & 127;
        const int cg    = ((tile & 63) << 2) + (local >> 5);
        const int j     = local & 31;
        const float* pj = cg_xyz + (size_t)(b * NCG + 1 + j) * 3;
        const float* pc = cg_xyz + (size_t)(b * NCG + cg) * 3;
        float d0 = pj[0] - pc[0], d1 = pj[1] - pc[1], d2 = pj[2] - pc[2];
        dv[r*4+0] = d0; dv[r*4+1] = d1; dv[r*4+2] = d2; dv[r*4+3] = 0.f;
        dist[r] = sqrtf(d0*d0 + d1*d1 + d2*d2);
    }

    // prefetch layer 0 weights
    for (int i = t; i < 2176; i += THREADS)
        cp_async16(sb + OFF_W + i * 16, g_Whf + i * 4);
    cp_async_commit();
    __syncthreads();

    // RBF expansion -> X[tau] (fp16), 1024 (row,half) units
    {
        const float delta = 10.0f / 127.0f;
        const float coeff = -0.5f / (delta * delta);
        for (int u = t; u < NTILES * 256; u += THREADS) {
            const int r    = u >> 1;
            const int half = (u & 1) * 64;
            const int tau  = r >> 7;
            const int lrow = r & 127;
            const float dr = dist[r];
            uint32_t* xp = (uint32_t*)(smem + OFF_X + tau * MATB)
                         + (lrow * LDX + half) / 2;
            #pragma unroll 8
            for (int j = 0; j < 32; j++) {
                const int col = half + 2 * j;
                const float x0 = dr - (float)col * delta;
                const float x1 = dr - (float)(col + 1) * delta;
                xp[j] = pack_f16x2(expf(coeff * x0 * x0), expf(coeff * x1 * x1));
            }
        }
    }
    cp_async_wait<0>();
    __syncthreads();

    const uint32_t bBase = sb + OFF_W + (uint32_t)(r16 * LDX + wn * 64 + c8) * 2;

    #pragma unroll 1
    for (int d = 0; d < NLAYER; d++) {
        // per-layer bias into smem (read at epilogues, before end-of-layer sync)
        if (t < KF) biasS[t] = g_bias[d * KF + t];

        // load this layer's B fragments into registers (weight-stationary)
        uint32_t B[8][4][4];
        #pragma unroll
        for (int kk = 0; kk < 8; kk++)
            #pragma unroll
            for (int ng = 0; ng < 4; ng++)
                ldsm_x4_t(B[kk][ng],
                          bBase + (uint32_t)(kk * 16 * LDX + ng * 16) * 2);

        __syncthreads();   // all warps done reading Wbuf (and biasS visible)

        // overwrite Wbuf with next layer's weights, overlapping 4 tiles of compute
        if (d + 1 < NLAYER) {
            const uint32_t* src = g_Whf + (d + 1) * MATU32;
            for (int i = t; i < 2176; i += THREADS)
                cp_async16(sb + OFF_W + i * 16, src + i * 4);
            cp_async_commit();
        }

        const bool relu   = ((d & 1) == 0);
        const bool domean = (d < 12) && ((d & 3) == 1);

        #pragma unroll 1
        for (int tau = 0; tau < NTILES; tau++) {
            const uint32_t xb = sb + OFF_X + tau * MATB;
            const uint32_t aBase0 = xb + (uint32_t)((wm * 32 + r16) * LDX + c8) * 2;
            const uint32_t aBase1 = xb + (uint32_t)((wm * 32 + 16 + r16) * LDX + c8) * 2;

            float acc[2][8][4];
            #pragma unroll
            for (int mt = 0; mt < 2; mt++)
                #pragma unroll
                for (int nt = 0; nt < 8; nt++)
                    #pragma unroll
                    for (int q = 0; q < 4; q++) acc[mt][nt][q] = 0.f;

            uint32_t a0[4], a1[4], n0v[4], n1v[4];
            ldsm_x4(a0, aBase0);
            ldsm_x4(a1, aBase1);

            #pragma unroll
            for (int kk = 0; kk < 8; kk++) {
                if (kk < 7) {
                    ldsm_x4(n0v, aBase0 + (uint32_t)((kk + 1) * 16) * 2);
                    ldsm_x4(n1v, aBase1 + (uint32_t)((kk + 1) * 16) * 2);
                }
                #pragma unroll
                for (int ng = 0; ng < 4; ng++) {
                    mma_f16(acc[0][2*ng],   a0, &B[kk][ng][0]);
                    mma_f16(acc[0][2*ng+1], a0, &B[kk][ng][2]);
                    mma_f16(acc[1][2*ng],   a1, &B[kk][ng][0]);
                    mma_f16(acc[1][2*ng+1], a1, &B[kk][ng][2]);
                }
                if (kk < 7) {
                    #pragma unroll
                    for (int q = 0; q < 4; q++) { a0[q] = n0v[q]; a1[q] = n1v[q]; }
                }
            }

            // partner warp done reading X[tau] rows -> safe to overwrite after epilogue
            pair_bar(wm);

            // bias + relu
            #pragma unroll
            for (int nt = 0; nt < 8; nt++) {
                const int c = wn * 64 + nt * 8 + tig * 2;
                const float b0 = biasS[c], b1 = biasS[c + 1];
                #pragma unroll
                for (int mt = 0; mt < 2; mt++) {
                    acc[mt][nt][0] += b0; acc[mt][nt][1] += b1;
                    acc[mt][nt][2] += b0; acc[mt][nt][3] += b1;
                    if (relu) {
                        acc[mt][nt][0] = fmaxf(acc[mt][nt][0], 0.f);
                        acc[mt][nt][1] = fmaxf(acc[mt][nt][1], 0.f);
                        acc[mt][nt][2] = fmaxf(acc[mt][nt][2], 0.f);
                        acc[mt][nt][3] = fmaxf(acc[mt][nt][3], 0.f);
                    }
                }
            }

            // KNN-mean (this warp's 32 rows = one cg group)
            if (domean) {
                #pragma unroll
                for (int nt = 0; nt < 8; nt++) {
                    float s0 = acc[0][nt][0] + acc[0][nt][2] + acc[1][nt][0] + acc[1][nt][2];
                    float s1 = acc[0][nt][1] + acc[0][nt][3] + acc[1][nt][1] + acc[1][nt][3];
                    #pragma unroll
                    for (int m = 4; m <= 16; m <<= 1) {
                        s0 += __shfl_xor_sync(0xffffffffu, s0, m);
                        s1 += __shfl_xor_sync(0xffffffffu, s1, m);
                    }
                    s0 *= (1.0f / 32.0f);
                    s1 *= (1.0f / 32.0f);
                    #pragma unroll
                    for (int mt = 0; mt < 2; mt++) {
                        acc[mt][nt][0] += s0; acc[mt][nt][2] += s0;
                        acc[mt][nt][1] += s1; acc[mt][nt][3] += s1;
                    }
                }
            }

            if (d < 12) {
                uint32_t* X = (uint32_t*)(smem + OFF_X + tau * MATB);
                #pragma unroll
                for (int mt = 0; mt < 2; mt++) {
                    const int r0 = 32 * wm + 16 * mt + grp;
                    #pragma unroll
                    for (int nt = 0; nt < 8; nt++) {
                        const int c = wn * 64 + nt * 8 + tig * 2;
                        X[(r0 * LDX + c) / 2]       = pack_f16x2(acc[mt][nt][0], acc[mt][nt][1]);
                        X[((r0 + 8) * LDX + c) / 2] = pack_f16x2(acc[mt][nt][2], acc[mt][nt][3]);
                    }
                }
            } else {
                // G[b][col][n] += sum_rows F[row][col] * dv[row][n]
                const int rbase = tau * 128;
                float dvc[2][2][3];
                #pragma unroll
                for (int mt = 0; mt < 2; mt++) {
                    const int r0 = rbase + 32 * wm + 16 * mt + grp;
                    #pragma unroll
                    for (int h = 0; h < 2; h++) {
                        dvc[mt][h][0] = dv[(r0 + 8*h) * 4 + 0];
                        dvc[mt][h][1] = dv[(r0 + 8*h) * 4 + 1];
                        dvc[mt][h][2] = dv[(r0 + 8*h) * 4 + 2];
                    }
                }
                #pragma unroll
                for (int nt = 0; nt < 8; nt++) {
                    float g0[3] = {0.f,0.f,0.f}, g1[3] = {0.f,0.f,0.f};
                    #pragma unroll
                    for (int mt = 0; mt < 2; mt++)
                        #pragma unroll
                        for (int n = 0; n < 3; n++) {
                            g0[n] += acc[mt][nt][0] * dvc[mt][0][n]
                                   + acc[mt][nt][2] * dvc[mt][1][n];
                            g1[n] += acc[mt][nt][1] * dvc[mt][0][n]
                                   + acc[mt][nt][3] * dvc[mt][1][n];
                        }
                    #pragma unroll
                    for (int m = 4; m <= 16; m <<= 1)
                        #pragma unroll
                        for (int n = 0; n < 3; n++) {
                            g0[n] += __shfl_xor_sync(0xffffffffu, g0[n], m);
                            g1[n] += __shfl_xor_sync(0xffffffffu, g1[n], m);
                        }
                    if (grp == 0) {
                        const int c = wn * 64 + nt * 8 + tig * 2;
                        float* gp = g_G + (size_t)(b * KF + c) * 3;
                        atomicAdd(gp + 0, g0[0]);
                        atomicAdd(gp + 1, g0[1]);
                        atomicAdd(gp + 2, g0[2]);
                        atomicAdd(gp + 3, g1[0]);
                        atomicAdd(gp + 4, g1[1]);
                        atomicAdd(gp + 5, g1[2]);
                    }
                }
            }
        } // tiles

        cp_async_wait<0>();
        __syncthreads();   // next-layer W landed; X writes visible
    } // layers

    if (t < 3) {
        float s = 0.f;
        for (int r = 0; r < NTILES * 128; r++) s += dv[r * 4 + t];
        atomicAdd(&g_S[b * 3 + t], s);
    }
}

// ---------------- dx_recon = G @ dec_W2 + dec_b2 * S (split-K, atomic) ----------------
__global__ void dx_kernel(const float* __restrict__ dec_W2,
                          const float* __restrict__ dec_b2) {
    __shared__ float Gs[32 * 3];
    __shared__ float Ss[3];
    const int b     = blockIdx.x >> 4;
    const int chunk = (blockIdx.x >> 2) & 3;
    const int oc    = blockIdx.x & 3;
    const int o     = (oc << 8) + threadIdx.x;
    if (threadIdx.x < 96)
        Gs[threadIdx.x] = g_G[b * KF * 3 + chunk * 96 + threadIdx.x];
    if (threadIdx.x < 3) Ss[threadIdx.x] = g_S[b * 3 + threadIdx.x];
    __syncthreads();
    float d0 = 0.f, d1 = 0.f, d2 = 0.f;
    #pragma unroll 8
    for (int kk = 0; kk < 32; kk++) {
        const float w = dec_W2[(size_t)(chunk * 32 + kk) * NATOMS + o];
        d0 = fmaf(Gs[kk*3+0], w, d0);
        d1 = fmaf(Gs[kk*3+1], w, d1);
        d2 = fmaf(Gs[kk*3+2], w, d2);
    }
    if (chunk == 0) {
        const float bb = dec_b2[o];
        d0 += bb * Ss[0]; d1 += bb * Ss[1]; d2 += bb * Ss[2];
    }
    float* p = g_dx + (size_t)(b * NATOMS + o) * 3;
    atomicAdd(p + 0, d0);
    atomicAdd(p + 1, d1);
    atomicAdd(p + 2, d2);
}

// ---------------- cg_offset (32-atom chunks, grid = 16*32) ----------------
__global__ void cgoff_kernel(const float* __restrict__ assign_norm) {
    __shared__ float dxs[32 * 3];
    const int b  = blockIdx.x >> 5;
    const int oc = blockIdx.x & 31;
    const int j  = threadIdx.x;
    const int obase = oc * 32;
    if (threadIdx.x < 96)
        dxs[threadIdx.x] = g_dx[(size_t)(b * NATOMS + obase) * 3 + threadIdx.x];
    __syncthreads();
    float a0 = 0.f, a1 = 0.f, a2 = 0.f;
    #pragma unroll 4
    for (int oo = 0; oo < 32; oo++) {
        const float an = assign_norm[((size_t)b * NATOMS + obase + oo) * NCG + j];
        a0 = fmaf(an, dxs[oo*3+0], a0);
        a1 = fmaf(an, dxs[oo*3+1], a1);
        a2 = fmaf(an, dxs[oo*3+2], a2);
    }
    atomicAdd(&g_cgoff[(b * NCG + j) * 3 + 0], a0);
    atomicAdd(&g_cgoff[(b * NCG + j) * 3 + 1], a1);
    atomicAdd(&g_cgoff[(b * NCG + j) * 3 + 2], a2);
}

// ---------------- xyz_recon ----------------
__global__ void recon_kernel(const float* __restrict__ cg_xyz,
                             const int* __restrict__ assign_idx,
                             float* __restrict__ out) {
    const int i = blockIdx.x * blockDim.x + threadIdx.x;
    if (i >= BB * NATOMS) return;
    const int b = i >> 10;
    const int o = i & 1023;
    const int ai = assign_idx[o];
    const float* cx = cg_xyz + (size_t)(b * NCG + ai) * 3;
    const float* co = g_cgoff + (size_t)(b * NCG + ai) * 3;
    const float* dx = g_dx + (size_t)i * 3;
    float* po = out + (size_t)BB * NATOMS * NCG + (size_t)BB * NATOMS * 3 + (size_t)i * 3;
    po[0] = cx[0] - co[0] + dx[0];
    po[1] = cx[1] - co[1] + dx[1];
    po[2] = cx[2] - co[2] + dx[2];
}

// ---------------- launch ----------------
extern "C" void kernel_launch(void* const* d_in, const int* in_sizes, int n_in,
                              void* d_out, int out_size) {
    const float* soft_assign = (const float*)d_in[0];
    const float* xyz         = (const float*)d_in[1];
    const float* cg_xyz      = (const float*)d_in[2];
    const float* assign_norm = (const float*)d_in[3];
    const int*   assign_idx  = (const int*)d_in[4];
    const float* mlp_W1 = (const float*)d_in[5];
    const float* mlp_b1 = (const float*)d_in[6];
    const float* mlp_W2 = (const float*)d_in[7];
    const float* mlp_b2 = (const float*)d_in[8];
    const float* upd_W1 = (const float*)d_in[9];
    const float* upd_b1 = (const float*)d_in[10];
    const float* upd_W2 = (const float*)d_in[11];
    const float* upd_b2 = (const float*)d_in[12];
    const float* dec_W1 = (const float*)d_in[13];
    const float* dec_b1 = (const float*)d_in[14];
    const float* dec_W2 = (const float*)d_in[15];
    const float* dec_b2 = (const float*)d_in[16];

    float* out = (float*)d_out;

    static cudaStream_t s2 = nullptr, s3 = nullptr;
    static cudaEvent_t evFork = nullptr, evJoin = nullptr, evZero = nullptr;
    if (s2 == nullptr) {
        cudaStreamCreateWithFlags(&s2, cudaStreamNonBlocking);
        cudaStreamCreateWithFlags(&s3, cudaStreamNonBlocking);
        cudaEventCreateWithFlags(&evFork, cudaEventDisableTiming);
        cudaEventCreateWithFlags(&evJoin, cudaEventDisableTiming);
        cudaEventCreateWithFlags(&evZero, cudaEventDisableTiming);
    }

    // fork: passthrough copies (s2) + scratch zeroing (s3) overlap compute chain
    cudaEventRecord(evFork, 0);
    cudaStreamWaitEvent(s2, evFork, 0);
    cudaStreamWaitEvent(s3, evFork, 0);
    cudaMemcpyAsync(out, soft_assign, (size_t)BB * NATOMS * NCG * sizeof(float),
                    cudaMemcpyDeviceToDevice, s2);
    cudaMemcpyAsync(out + (size_t)BB * NATOMS * NCG, xyz,
                    (size_t)BB * NATOMS * 3 * sizeof(float),
                    cudaMemcpyDeviceToDevice, s2);
    cudaEventRecord(evJoin, s2);
    zero_kernel<<<32, 256, 0, s3>>>();
    cudaEventRecord(evZero, s3);

    convert_kernel<<<(NWQUAD + NLAYER * KF + 255) / 256, 256>>>(
        mlp_W1, mlp_b1, mlp_W2, mlp_b2,
        upd_W1, upd_b1, upd_W2, upd_b2, dec_W1, dec_b1);

    cudaStreamWaitEvent(0, evZero, 0);
    cudaFuncSetAttribute(fused_kernel, cudaFuncAttributeMaxDynamicSharedMemorySize,
                         SMEM_TOTAL);
    fused_kernel<<<BB * NCG / (4 * NTILES), THREADS, SMEM_TOTAL>>>(cg_xyz);

    dx_kernel<<<BB * 16, 256>>>(dec_W2, dec_b2);
    cgoff_kernel<<<BB * 32, 256>>>(assign_norm);
    recon_kernel<<<(BB * NATOMS + 255) / 256, 256>>>(cg_xyz, assign_idx, out);

    cudaStreamWaitEvent(0, evJoin, 0);
}

// round 15
// speedup vs baseline: 1.0508x; 1.0508x over previous
#include <cuda_runtime.h>
#include <cuda_fp16.h>
#include <math.h>
#include <stdint.h>

// Problem constants
#define BB      16
#define NCG     256
#define NATOMS  1024
#define KF      128
#define NLAYER  13
#define THREADS 256

#define LDX     136            // padded fp16 row stride (272 B)
#define MATU32  8704           // 128*68 u32 per fp16 matrix
#define MATB    34816          // bytes per matrix

// ---- smem byte offsets (total 113664 -> 2 CTAs/SM) ----
#define OFF_X     0            // 128 x 136 fp16 = 34816
#define OFF_W     34816        // 2 bufs x 34816 = 69632
#define OFF_DV    104448       // 128*4 f32 = 2048
#define OFF_DIST  106496       // 128 f32 = 512
#define OFF_BIAS  107008       // 13*128 f32 = 6656
#define SMEM_TOTAL 113664

// -------- device scratch (no allocs) --------
__device__ __align__(16) uint32_t g_Whf[NLAYER * MATU32]; // fp16 [l][k][68]
__device__ float g_bias[NLAYER * KF];
__device__ float g_G[BB * KF * 3];
__device__ float g_S[BB * 3];
__device__ float g_dx[BB * NATOMS * 3];
__device__ float g_cgoff[BB * NCG * 3];

// ---------------- helpers ----------------
__device__ __forceinline__ uint32_t smem_u32(const void* p) {
    uint32_t a;
    asm("{ .reg .u64 t; cvta.to.shared.u64 t, %1; cvt.u32.u64 %0, t; }"
        : "=r"(a) : "l"(p));
    return a;
}
// pack (e0, e1) -> fp16x2 with e0 in LOW half
__device__ __forceinline__ uint32_t pack_f16x2(float e0, float e1) {
    uint32_t r;
    asm("cvt.rn.f16x2.f32 %0, %1, %2;" : "=r"(r) : "f"(e1), "f"(e0));
    return r;
}
__device__ __forceinline__ void cp_async16(uint32_t smem_addr, const void* gptr) {
    asm volatile("cp.async.cg.shared.global [%0], [%1], 16;"
                 :: "r"(smem_addr), "l"(gptr));
}
__device__ __forceinline__ void cp_async_commit() {
    asm volatile("cp.async.commit_group;");
}
template <int N>
__device__ __forceinline__ void cp_async_wait() {
    asm volatile("cp.async.wait_group %0;" :: "n"(N));
}
__device__ __forceinline__ void ldsm_x4(uint32_t* r, uint32_t addr) {
    asm volatile("ldmatrix.sync.aligned.m8n8.x4.shared.b16 {%0,%1,%2,%3}, [%4];"
                 : "=r"(r[0]), "=r"(r[1]), "=r"(r[2]), "=r"(r[3]) : "r"(addr));
}
__device__ __forceinline__ void ldsm_x4_t(uint32_t* r, uint32_t addr) {
    asm volatile("ldmatrix.sync.aligned.m8n8.x4.trans.shared.b16 {%0,%1,%2,%3}, [%4];"
                 : "=r"(r[0]), "=r"(r[1]), "=r"(r[2]), "=r"(r[3]) : "r"(addr));
}
__device__ __forceinline__ void mma_f16(float* d, const uint32_t* a, const uint32_t* b) {
    asm volatile(
        "mma.sync.aligned.m16n8k16.row.col.f32.f16.f16.f32 "
        "{%0,%1,%2,%3},{%4,%5,%6,%7},{%8,%9},{%0,%1,%2,%3};"
        : "+f"(d[0]), "+f"(d[1]), "+f"(d[2]), "+f"(d[3])
        : "r"(a[0]), "r"(a[1]), "r"(a[2]), "r"(a[3]), "r"(b[0]), "r"(b[1]));
}
// pair barrier: warps 2*wm and 2*wm+1 (DIFFERENT SMSPs), ids 1..4
__device__ __forceinline__ void pair_bar(int wm) {
    asm volatile("bar.sync %0, 64;" :: "r"(wm + 1) : "memory");
}

// ---------------- zero scratch ----------------
__global__ void zero_kernel() {
    const int n1 = BB * KF * 3, n2 = BB * 3, n3 = BB * NCG * 3;
    const int n4 = BB * NATOMS * 3;
    const int total = n1 + n2 + n3 + n4;
    for (int i = blockIdx.x * blockDim.x + threadIdx.x; i < total;
         i += gridDim.x * blockDim.x) {
        if (i < n1)                 g_G[i] = 0.f;
        else if (i < n1 + n2)       g_S[i - n1] = 0.f;
        else if (i < n1 + n2 + n3)  g_cgoff[i - n1 - n2] = 0.f;
        else                        g_dx[i - n1 - n2 - n3] = 0.f;
    }
}

// ---------------- weight select ----------------
__device__ __forceinline__ const float* layer_W(
    int d, const float* mW1, const float* mW2, const float* uW1,
    const float* uW2, const float* dW1) {
    if (d == 12) return dW1;
    const int g = d >> 2, ty = d & 3;
    const size_t o = (size_t)g * KF * KF;
    if (ty == 0) return mW1 + o;
    if (ty == 1) return mW2 + o;
    if (ty == 2) return uW1 + o;
    return uW2 + o;
}
__device__ __forceinline__ const float* layer_b(
    int d, const float* mb1, const float* mb2, const float* ub1,
    const float* ub2, const float* db1) {
    if (d == 12) return db1;
    const int g = d >> 2, ty = d & 3;
    const size_t o = (size_t)g * KF;
    if (ty == 0) return mb1 + o;
    if (ty == 1) return mb2 + o;
    if (ty == 2) return ub1 + o;
    return ub2 + o;
}

#define NWQUAD (NLAYER * KF * 32)   // 53248 col-quads

__global__ void convert_kernel(const float* mW1, const float* mb1,
                               const float* mW2, const float* mb2,
                               const float* uW1, const float* ub1,
                               const float* uW2, const float* ub2,
                               const float* dW1, const float* db1) {
    const int i = blockIdx.x * blockDim.x + threadIdx.x;
    if (i < NWQUAD) {
        const int d   = i / (KF * 32);
        const int rem = i % (KF * 32);
        const int k   = rem >> 5;
        const int cq  = rem & 31;
        const float* W = layer_W(d, mW1, mW2, uW1, uW2, dW1);
        const float4 w = *(const float4*)(W + (size_t)k * KF + 4 * cq);
        const int base = d * MATU32 + k * 68 + 2 * cq;
        g_Whf[base]     = pack_f16x2(w.x, w.y);
        g_Whf[base + 1] = pack_f16x2(w.z, w.w);
    } else if (i < NWQUAD + NLAYER * KF) {
        const int j = i - NWQUAD;
        const int d = j >> 7, c = j & 127;
        g_bias[j] = layer_b(d, mb1, mb2, ub1, ub2, db1)[c];
    }
}

// ---------------- fused MLP chain (fp16 single-pass mma.sync) ----------------
extern __shared__ __align__(16) char smem[];

__global__ __launch_bounds__(THREADS, 2)
void fused_kernel(const float* __restrict__ cg_xyz) {
    const uint32_t sb = smem_u32(smem);
    const int t = threadIdx.x, wid = t >> 5, lane = t & 31;
    const int wm = wid >> 1;       // rows [32wm, 32wm+32); pair = adjacent wids
    const int wn = wid & 1;        // cols [64wn, 64wn+64); pair warps on DIFFERENT SMSPs
    const int grp = lane >> 2, tig = lane & 3;
    const int r16 = lane & 15, c8 = (lane >> 4) << 3;

    const int blk = blockIdx.x;
    const int b   = blk >> 6;
    const int cg0 = (blk & 63) * 4;

    float* dv   = (float*)(smem + OFF_DV);
    float* dist = (float*)(smem + OFF_DIST);
    float* bias = (float*)(smem + OFF_BIAS);

    // phase 0: dv / dist (row = cg_local*32 + j)
    if (t < 128) {
        const int cg = cg0 + (t >> 5);
        const int j  = t & 31;
        const float* pj = cg_xyz + (size_t)(b * NCG + 1 + j) * 3;
        const float* pc = cg_xyz + (size_t)(b * NCG + cg) * 3;
        float d0 = pj[0] - pc[0], d1 = pj[1] - pc[1], d2 = pj[2] - pc[2];
        dv[t*4+0] = d0; dv[t*4+1] = d1; dv[t*4+2] = d2; dv[t*4+3] = 0.f;
        dist[t] = sqrtf(d0*d0 + d1*d1 + d2*d2);
    }
    for (int i = t; i < NLAYER * KF; i += THREADS) bias[i] = g_bias[i];

    // prefetch layer 0 weights (34816 B = 2176 x 16B)
    for (int i = t; i < 2176; i += THREADS)
        cp_async16(sb + OFF_W + i * 16, g_Whf + i * 4);
    cp_async_commit();
    __syncthreads();

    // RBF expansion -> X (fp16)
    {
        const float delta = 10.0f / 127.0f;
        const float coeff = -0.5f / (delta * delta);
        const int row = t >> 1, half = (t & 1) * 64;
        const float dr = dist[row];
        uint32_t* xp = (uint32_t*)(smem + OFF_X) + (row * LDX + half) / 2;
        #pragma unroll 8
        for (int j = 0; j < 32; j++) {
            const int col = half + 2 * j;
            const float x0 = dr - (float)col * delta;
            const float x1 = dr - (float)(col + 1) * delta;
            xp[j] = pack_f16x2(expf(coeff * x0 * x0), expf(coeff * x1 * x1));
        }
    }
    cp_async_wait<0>();
    __syncthreads();

    const uint32_t aRowBase0 = (uint32_t)((wm * 32 + r16) * LDX + c8) * 2;
    const uint32_t aRowBase1 = (uint32_t)((wm * 32 + 16 + r16) * LDX + c8) * 2;
    const uint32_t bRowBase  = (uint32_t)(r16 * LDX + wn * 64 + c8) * 2;

    #pragma unroll 1
    for (int d = 0; d < NLAYER; d++) {
        // prefetch next layer's weights into the other buffer
        if (d + 1 < NLAYER) {
            const uint32_t* src = g_Whf + (d + 1) * MATU32;
            const uint32_t dst = sb + OFF_W + ((d + 1) & 1) * MATB;
            for (int i = t; i < 2176; i += THREADS)
                cp_async16(dst + i * 16, src + i * 4);
            cp_async_commit();
        }

        const uint32_t wb = sb + OFF_W + (d & 1) * MATB + bRowBase;

        float acc[2][8][4];
        #pragma unroll
        for (int mt = 0; mt < 2; mt++)
            #pragma unroll
            for (int nt = 0; nt < 8; nt++)
                #pragma unroll
                for (int q = 0; q < 4; q++) acc[mt][nt][q] = 0.f;

        // software-pipelined A and B fragments
        uint32_t a[2][4], an[2][4], bb0[4], bb1[4];
        ldsm_x4(a[0], sb + OFF_X + aRowBase0);
        ldsm_x4(a[1], sb + OFF_X + aRowBase1);
        ldsm_x4_t(bb0, wb);   // (kk=0, ng=0)

        #pragma unroll
        for (int kk = 0; kk < 8; kk++) {
            const uint32_t wk = wb + (uint32_t)(kk * 16 * LDX) * 2;
            if (kk < 7) {
                ldsm_x4(an[0], sb + OFF_X + aRowBase0 + (uint32_t)((kk + 1) * 16) * 2);
                ldsm_x4(an[1], sb + OFF_X + aRowBase1 + (uint32_t)((kk + 1) * 16) * 2);
            }
            #pragma unroll
            for (int ng = 0; ng < 4; ng++) {
                uint32_t* cur = ((ng & 1) == 0) ? bb0 : bb1;
                uint32_t* nxt = ((ng & 1) == 0) ? bb1 : bb0;
                if (ng < 3)
                    ldsm_x4_t(nxt, wk + (uint32_t)((ng + 1) * 16) * 2);
                else if (kk < 7)
                    ldsm_x4_t(nxt, wb + (uint32_t)((kk + 1) * 16 * LDX) * 2);
                mma_f16(acc[0][2*ng],   a[0], &cur[0]);
                mma_f16(acc[0][2*ng+1], a[0], &cur[2]);
                mma_f16(acc[1][2*ng],   a[1], &cur[0]);
                mma_f16(acc[1][2*ng+1], a[1], &cur[2]);
            }
            if (kk < 7) {
                #pragma unroll
                for (int q = 0; q < 4; q++) { a[0][q] = an[0][q]; a[1][q] = an[1][q]; }
            }
        }

        // X reads done -> release partner early; barrier hides under epilogue
        pair_bar(wm);

        // bias + relu
        const bool relu = ((d & 1) == 0);
        const float* bl_ = bias + d * KF;
        #pragma unroll
        for (int nt = 0; nt < 8; nt++) {
            const int c = wn * 64 + nt * 8 + tig * 2;
            const float b0 = bl_[c], b1 = bl_[c + 1];
            #pragma unroll
            for (int mt = 0; mt < 2; mt++) {
                acc[mt][nt][0] += b0; acc[mt][nt][1] += b1;
                acc[mt][nt][2] += b0; acc[mt][nt][3] += b1;
                if (relu) {
                    acc[mt][nt][0] = fmaxf(acc[mt][nt][0], 0.f);
                    acc[mt][nt][1] = fmaxf(acc[mt][nt][1], 0.f);
                    acc[mt][nt][2] = fmaxf(acc[mt][nt][2], 0.f);
                    acc[mt][nt][3] = fmaxf(acc[mt][nt][3], 0.f);
                }
            }
        }

        // KNN-mean (this warp's 32 rows = one cg group)
        if (d < 12 && (d & 3) == 1) {
            #pragma unroll
            for (int nt = 0; nt < 8; nt++) {
                float s0 = acc[0][nt][0] + acc[0][nt][2] + acc[1][nt][0] + acc[1][nt][2];
                float s1 = acc[0][nt][1] + acc[0][nt][3] + acc[1][nt][1] + acc[1][nt][3];
                #pragma unroll
                for (int m = 4; m <= 16; m <<= 1) {
                    s0 += __shfl_xor_sync(0xffffffffu, s0, m);
                    s1 += __shfl_xor_sync(0xffffffffu, s1, m);
                }
                s0 *= (1.0f / 32.0f);
                s1 *= (1.0f / 32.0f);
                #pragma unroll
                for (int mt = 0; mt < 2; mt++) {
                    acc[mt][nt][0] += s0; acc[mt][nt][2] += s0;
                    acc[mt][nt][1] += s1; acc[mt][nt][3] += s1;
                }
            }
        }

        if (d < 12) {
            // write activations back as fp16 pairs
            uint32_t* X = (uint32_t*)(smem + OFF_X);
            #pragma unroll
            for (int mt = 0; mt < 2; mt++) {
                const int r0 = 32 * wm + 16 * mt + grp;
                #pragma unroll
                for (int nt = 0; nt < 8; nt++) {
                    const int c = wn * 64 + nt * 8 + tig * 2;
                    X[(r0 * LDX + c) / 2]       = pack_f16x2(acc[mt][nt][0], acc[mt][nt][1]);
                    X[((r0 + 8) * LDX + c) / 2] = pack_f16x2(acc[mt][nt][2], acc[mt][nt][3]);
                }
            }
        } else {
            // G[b][col][n] += sum_rows F[row][col] * dv[row][n]
            float dvc[2][2][3];
            #pragma unroll
            for (int mt = 0; mt < 2; mt++) {
                const int r0 = 32 * wm + 16 * mt + grp;
                #pragma unroll
                for (int h = 0; h < 2; h++) {
                    dvc[mt][h][0] = dv[(r0 + 8*h) * 4 + 0];
                    dvc[mt][h][1] = dv[(r0 + 8*h) * 4 + 1];
                    dvc[mt][h][2] = dv[(r0 + 8*h) * 4 + 2];
                }
            }
            #pragma unroll
            for (int nt = 0; nt < 8; nt++) {
                float g0[3] = {0.f,0.f,0.f}, g1[3] = {0.f,0.f,0.f};
                #pragma unroll
                for (int mt = 0; mt < 2; mt++)
                    #pragma unroll
                    for (int n = 0; n < 3; n++) {
                        g0[n] += acc[mt][nt][0] * dvc[mt][0][n]
                               + acc[mt][nt][2] * dvc[mt][1][n];
                        g1[n] += acc[mt][nt][1] * dvc[mt][0][n]
                               + acc[mt][nt][3] * dvc[mt][1][n];
                    }
                #pragma unroll
                for (int m = 4; m <= 16; m <<= 1)
                    #pragma unroll
                    for (int n = 0; n < 3; n++) {
                        g0[n] += __shfl_xor_sync(0xffffffffu, g0[n], m);
                        g1[n] += __shfl_xor_sync(0xffffffffu, g1[n], m);
                    }
                if (grp == 0) {
                    const int c = wn * 64 + nt * 8 + tig * 2;
                    float* gp = g_G + (size_t)(b * KF + c) * 3;
                    atomicAdd(gp + 0, g0[0]);
                    atomicAdd(gp + 1, g0[1]);
                    atomicAdd(gp + 2, g0[2]);
                    atomicAdd(gp + 3, g1[0]);
                    atomicAdd(gp + 4, g1[1]);
                    atomicAdd(gp + 5, g1[2]);
                }
            }
        }

        cp_async_wait<0>();
        __syncthreads();   // X writes + W buffer visible CTA-wide
    }

    // S[b][n] += sum_rows dv[row][n]  (parallel: 3 warps, shuffle reduce)
    if (t < 96) {
        const int n = t >> 5;         // warp -> component
        const int l = t & 31;
        float s = dv[l * 4 + n] + dv[(l + 32) * 4 + n]
                + dv[(l + 64) * 4 + n] + dv[(l + 96) * 4 + n];
        #pragma unroll
        for (int m = 16; m >= 1; m >>= 1)
            s += __shfl_xor_sync(0xffffffffu, s, m);
        if (l == 0) atomicAdd(&g_S[b * 3 + n], s);
    }
}

// ---------------- dx_recon = G @ dec_W2 + dec_b2 * S (split-K, atomic) ----------------
__global__ void dx_kernel(const float* __restrict__ dec_W2,
                          const float* __restrict__ dec_b2) {
    __shared__ float Gs[32 * 3];
    __shared__ float Ss[3];
    const int b     = blockIdx.x >> 4;
    const int chunk = (blockIdx.x >> 2) & 3;
    const int oc    = blockIdx.x & 3;
    const int o     = (oc << 8) + threadIdx.x;
    if (threadIdx.x < 96)
        Gs[threadIdx.x] = g_G[b * KF * 3 + chunk * 96 + threadIdx.x];
    if (threadIdx.x < 3) Ss[threadIdx.x] = g_S[b * 3 + threadIdx.x];
    __syncthreads();
    float d0 = 0.f, d1 = 0.f, d2 = 0.f;
    #pragma unroll 8
    for (int kk = 0; kk < 32; kk++) {
        const float w = dec_W2[(size_t)(chunk * 32 + kk) * NATOMS + o];
        d0 = fmaf(Gs[kk*3+0], w, d0);
        d1 = fmaf(Gs[kk*3+1], w, d1);
        d2 = fmaf(Gs[kk*3+2], w, d2);
    }
    if (chunk == 0) {
        const float bb = dec_b2[o];
        d0 += bb * Ss[0]; d1 += bb * Ss[1]; d2 += bb * Ss[2];
    }
    float* p = g_dx + (size_t)(b * NATOMS + o) * 3;
    atomicAdd(p + 0, d0);
    atomicAdd(p + 1, d1);
    atomicAdd(p + 2, d2);
}

// ---------------- cg_offset (32-atom chunks, grid = 16*32) ----------------
__global__ void cgoff_kernel(const float* __restrict__ assign_norm) {
    __shared__ float dxs[32 * 3];
    const int b  = blockIdx.x >> 5;
    const int oc = blockIdx.x & 31;
    const int j  = threadIdx.x;
    const int obase = oc * 32;
    if (threadIdx.x < 96)
        dxs[threadIdx.x] = g_dx[(size_t)(b * NATOMS + obase) * 3 + threadIdx.x];
    __syncthreads();
    float a0 = 0.f, a1 = 0.f, a2 = 0.f;
    #pragma unroll 4
    for (int oo = 0; oo < 32; oo++) {
        const float an = assign_norm[((size_t)b * NATOMS + obase + oo) * NCG + j];
        a0 = fmaf(an, dxs[oo*3+0], a0);
        a1 = fmaf(an, dxs[oo*3+1], a1);
        a2 = fmaf(an, dxs[oo*3+2], a2);
    }
    atomicAdd(&g_cgoff[(b * NCG + j) * 3 + 0], a0);
    atomicAdd(&g_cgoff[(b * NCG + j) * 3 + 1], a1);
    atomicAdd(&g_cgoff[(b * NCG + j) * 3 + 2], a2);
}

// ---------------- xyz_recon ----------------
__global__ void recon_kernel(const float* __restrict__ cg_xyz,
                             const int* __restrict__ assign_idx,
                             float* __restrict__ out) {
    const int i = blockIdx.x * blockDim.x + threadIdx.x;
    if (i >= BB * NATOMS) return;
    const int b = i >> 10;
    const int o = i & 1023;
    const int ai = assign_idx[o];
    const float* cx = cg_xyz + (size_t)(b * NCG + ai) * 3;
    const float* co = g_cgoff + (size_t)(b * NCG + ai) * 3;
    const float* dx = g_dx + (size_t)i * 3;
    float* po = out + (size_t)BB * NATOMS * NCG + (size_t)BB * NATOMS * 3 + (size_t)i * 3;
    po[0] = cx[0] - co[0] + dx[0];
    po[1] = cx[1] - co[1] + dx[1];
    po[2] = cx[2] - co[2] + dx[2];
}

// ---------------- launch ----------------
extern "C" void kernel_launch(void* const* d_in, const int* in_sizes, int n_in,
                              void* d_out, int out_size) {
    const float* soft_assign = (const float*)d_in[0];
    const float* xyz         = (const float*)d_in[1];
    const float* cg_xyz      = (const float*)d_in[2];
    const float* assign_norm = (const float*)d_in[3];
    const int*   assign_idx  = (const int*)d_in[4];
    const float* mlp_W1 = (const float*)d_in[5];
    const float* mlp_b1 = (const float*)d_in[6];
    const float* mlp_W2 = (const float*)d_in[7];
    const float* mlp_b2 = (const float*)d_in[8];
    const float* upd_W1 = (const float*)d_in[9];
    const float* upd_b1 = (const float*)d_in[10];
    const float* upd_W2 = (const float*)d_in[11];
    const float* upd_b2 = (const float*)d_in[12];
    const float* dec_W1 = (const float*)d_in[13];
    const float* dec_b1 = (const float*)d_in[14];
    const float* dec_W2 = (const float*)d_in[15];
    const float* dec_b2 = (const float*)d_in[16];

    float* out = (float*)d_out;

    static cudaStream_t s2 = nullptr, s3 = nullptr;
    static cudaEvent_t evFork = nullptr, evJoin = nullptr, evZero = nullptr;
    if (s2 == nullptr) {
        cudaStreamCreateWithFlags(&s2, cudaStreamNonBlocking);
        cudaStreamCreateWithFlags(&s3, cudaStreamNonBlocking);
        cudaEventCreateWithFlags(&evFork, cudaEventDisableTiming);
        cudaEventCreateWithFlags(&evJoin, cudaEventDisableTiming);
        cudaEventCreateWithFlags(&evZero, cudaEventDisableTiming);
    }

    // fork: passthrough copies (s2) + scratch zeroing (s3) overlap compute chain
    cudaEventRecord(evFork, 0);
    cudaStreamWaitEvent(s2, evFork, 0);
    cudaStreamWaitEvent(s3, evFork, 0);
    cudaMemcpyAsync(out, soft_assign, (size_t)BB * NATOMS * NCG * sizeof(float),
                    cudaMemcpyDeviceToDevice, s2);
    cudaMemcpyAsync(out + (size_t)BB * NATOMS * NCG, xyz,
                    (size_t)BB * NATOMS * 3 * sizeof(float),
                    cudaMemcpyDeviceToDevice, s2);
    cudaEventRecord(evJoin, s2);
    zero_kernel<<<32, 256, 0, s3>>>();
    cudaEventRecord(evZero, s3);

    convert_kernel<<<(NWQUAD + NLAYER * KF + 255) / 256, 256>>>(
        mlp_W1, mlp_b1, mlp_W2, mlp_b2,
        upd_W1, upd_b1, upd_W2, upd_b2, dec_W1, dec_b1);

    cudaStreamWaitEvent(0, evZero, 0);   // fused needs zeroed scratch
    cudaFuncSetAttribute(fused_kernel, cudaFuncAttributeMaxDynamicSharedMemorySize,
                         SMEM_TOTAL);
    fused_kernel<<<BB * NCG / 4, THREADS, SMEM_TOTAL>>>(cg_xyz);

    dx_kernel<<<BB * 16, 256>>>(dec_W2, dec_b2);
    cgoff_kernel<<<BB * 32, 256>>>(assign_norm);
    recon_kernel<<<(BB * NATOMS + 255) / 256, 256>>>(cg_xyz, assign_idx, out);

    cudaStreamWaitEvent(0, evJoin, 0);
}

// round 16
// speedup vs baseline: 1.0617x; 1.0103x over previous
#include <cuda_runtime.h>
#include <cuda_fp16.h>
#include <math.h>
#include <stdint.h>

// Problem constants
#define BB      16
#define NCG     256
#define NATOMS  1024
#define KF      128
#define NLAYER  13
#define THREADS 256

#define LDX     136            // padded fp16 row stride (272 B)
#define MATU32  8704           // 128*68 u32 per fp16 matrix
#define MATB    34816          // bytes per matrix

// ---- smem byte offsets (total 113664 -> 2 CTAs/SM) ----
#define OFF_X     0            // 128 x 136 fp16 = 34816
#define OFF_W     34816        // 2 bufs x 34816 = 69632
#define OFF_DV    104448       // 128*4 f32 = 2048
#define OFF_DIST  106496       // 128 f32 = 512
#define OFF_BIAS  107008       // 13*128 f32 = 6656
#define SMEM_TOTAL 113664

// -------- device scratch (no allocs) --------
__device__ __align__(16) uint32_t g_Whf[NLAYER * MATU32]; // fp16 [l][k][68]
__device__ float g_bias[NLAYER * KF];
__device__ float g_G[BB * KF * 3];
__device__ float g_S[BB * 3];
__device__ float g_dx[BB * NATOMS * 3];
__device__ float g_cgoff[BB * NCG * 3];

// ---------------- helpers ----------------
__device__ __forceinline__ uint32_t smem_u32(const void* p) {
    uint32_t a;
    asm("{ .reg .u64 t; cvta.to.shared.u64 t, %1; cvt.u32.u64 %0, t; }"
        : "=r"(a) : "l"(p));
    return a;
}
// pack (e0, e1) -> fp16x2 with e0 in LOW half
__device__ __forceinline__ uint32_t pack_f16x2(float e0, float e1) {
    uint32_t r;
    asm("cvt.rn.f16x2.f32 %0, %1, %2;" : "=r"(r) : "f"(e1), "f"(e0));
    return r;
}
__device__ __forceinline__ void cp_async16(uint32_t smem_addr, const void* gptr) {
    asm volatile("cp.async.cg.shared.global [%0], [%1], 16;"
                 :: "r"(smem_addr), "l"(gptr));
}
__device__ __forceinline__ void cp_async_commit() {
    asm volatile("cp.async.commit_group;");
}
template <int N>
__device__ __forceinline__ void cp_async_wait() {
    asm volatile("cp.async.wait_group %0;" :: "n"(N));
}
__device__ __forceinline__ void ldsm_x4(uint32_t* r, uint32_t addr) {
    asm volatile("ldmatrix.sync.aligned.m8n8.x4.shared.b16 {%0,%1,%2,%3}, [%4];"
                 : "=r"(r[0]), "=r"(r[1]), "=r"(r[2]), "=r"(r[3]) : "r"(addr));
}
__device__ __forceinline__ void ldsm_x4_t(uint32_t* r, uint32_t addr) {
    asm volatile("ldmatrix.sync.aligned.m8n8.x4.trans.shared.b16 {%0,%1,%2,%3}, [%4];"
                 : "=r"(r[0]), "=r"(r[1]), "=r"(r[2]), "=r"(r[3]) : "r"(addr));
}
__device__ __forceinline__ void mma_f16(float* d, const uint32_t* a, const uint32_t* b) {
    asm volatile(
        "mma.sync.aligned.m16n8k16.row.col.f32.f16.f16.f32 "
        "{%0,%1,%2,%3},{%4,%5,%6,%7},{%8,%9},{%0,%1,%2,%3};"
        : "+f"(d[0]), "+f"(d[1]), "+f"(d[2]), "+f"(d[3])
        : "r"(a[0]), "r"(a[1]), "r"(a[2]), "r"(a[3]), "r"(b[0]), "r"(b[1]));
}
// pair barrier: warps 2*wm and 2*wm+1 (DIFFERENT SMSPs), ids 1..4
__device__ __forceinline__ void pair_bar(int wm) {
    asm volatile("bar.sync %0, 64;" :: "r"(wm + 1) : "memory");
}

// ---------------- zero scratch ----------------
__global__ void zero_kernel() {
    const int n1 = BB * KF * 3, n2 = BB * 3, n3 = BB * NCG * 3;
    const int n4 = BB * NATOMS * 3;
    const int total = n1 + n2 + n3 + n4;
    for (int i = blockIdx.x * blockDim.x + threadIdx.x; i < total;
         i += gridDim.x * blockDim.x) {
        if (i < n1)                 g_G[i] = 0.f;
        else if (i < n1 + n2)       g_S[i - n1] = 0.f;
        else if (i < n1 + n2 + n3)  g_cgoff[i - n1 - n2] = 0.f;
        else                        g_dx[i - n1 - n2 - n3] = 0.f;
    }
}

// ---------------- weight select ----------------
__device__ __forceinline__ const float* layer_W(
    int d, const float* mW1, const float* mW2, const float* uW1,
    const float* uW2, const float* dW1) {
    if (d == 12) return dW1;
    const int g = d >> 2, ty = d & 3;
    const size_t o = (size_t)g * KF * KF;
    if (ty == 0) return mW1 + o;
    if (ty == 1) return mW2 + o;
    if (ty == 2) return uW1 + o;
    return uW2 + o;
}
__device__ __forceinline__ const float* layer_b(
    int d, const float* mb1, const float* mb2, const float* ub1,
    const float* ub2, const float* db1) {
    if (d == 12) return db1;
    const int g = d >> 2, ty = d & 3;
    const size_t o = (size_t)g * KF;
    if (ty == 0) return mb1 + o;
    if (ty == 1) return mb2 + o;
    if (ty == 2) return ub1 + o;
    return ub2 + o;
}

#define NWQUAD (NLAYER * KF * 32)   // 53248 col-quads

__global__ void convert_kernel(const float* mW1, const float* mb1,
                               const float* mW2, const float* mb2,
                               const float* uW1, const float* ub1,
                               const float* uW2, const float* ub2,
                               const float* dW1, const float* db1) {
    const int i = blockIdx.x * blockDim.x + threadIdx.x;
    if (i < NWQUAD) {
        const int d   = i / (KF * 32);
        const int rem = i % (KF * 32);
        const int k   = rem >> 5;
        const int cq  = rem & 31;
        const float* W = layer_W(d, mW1, mW2, uW1, uW2, dW1);
        const float4 w = *(const float4*)(W + (size_t)k * KF + 4 * cq);
        const int base = d * MATU32 + k * 68 + 2 * cq;
        g_Whf[base]     = pack_f16x2(w.x, w.y);
        g_Whf[base + 1] = pack_f16x2(w.z, w.w);
    } else if (i < NWQUAD + NLAYER * KF) {
        const int j = i - NWQUAD;
        const int d = j >> 7, c = j & 127;
        g_bias[j] = layer_b(d, mb1, mb2, ub1, ub2, db1)[c];
    }
}

// ---------------- fused MLP chain (fp16 single-pass mma.sync) ----------------
extern __shared__ __align__(16) char smem[];

__global__ __launch_bounds__(THREADS, 2)
void fused_kernel(const float* __restrict__ cg_xyz) {
    const uint32_t sb = smem_u32(smem);
    const int t = threadIdx.x, wid = t >> 5, lane = t & 31;
    const int wm = wid >> 1;       // rows [32wm, 32wm+32); pair = adjacent wids
    const int wn = wid & 1;        // cols [64wn, 64wn+64); pair warps on DIFFERENT SMSPs
    const int grp = lane >> 2, tig = lane & 3;
    const int r16 = lane & 15, c8 = (lane >> 4) << 3;

    const int blk = blockIdx.x;
    const int b   = blk >> 6;
    const int cg0 = (blk & 63) * 4;

    float* dv   = (float*)(smem + OFF_DV);
    float* dist = (float*)(smem + OFF_DIST);
    float* bias = (float*)(smem + OFF_BIAS);

    // phase 0: dv / dist (row = cg_local*32 + j)
    if (t < 128) {
        const int cg = cg0 + (t >> 5);
        const int j  = t & 31;
        const float* pj = cg_xyz + (size_t)(b * NCG + 1 + j) * 3;
        const float* pc = cg_xyz + (size_t)(b * NCG + cg) * 3;
        float d0 = pj[0] - pc[0], d1 = pj[1] - pc[1], d2 = pj[2] - pc[2];
        dv[t*4+0] = d0; dv[t*4+1] = d1; dv[t*4+2] = d2; dv[t*4+3] = 0.f;
        dist[t] = sqrtf(d0*d0 + d1*d1 + d2*d2);
    }
    for (int i = t; i < NLAYER * KF; i += THREADS) bias[i] = g_bias[i];

    // prefetch layer 0 weights (34816 B = 2176 x 16B)
    for (int i = t; i < 2176; i += THREADS)
        cp_async16(sb + OFF_W + i * 16, g_Whf + i * 4);
    cp_async_commit();
    __syncthreads();

    // RBF expansion -> X (fp16)
    {
        const float delta = 10.0f / 127.0f;
        const float coeff = -0.5f / (delta * delta);
        const int row = t >> 1, half = (t & 1) * 64;
        const float dr = dist[row];
        uint32_t* xp = (uint32_t*)(smem + OFF_X) + (row * LDX + half) / 2;
        #pragma unroll 8
        for (int j = 0; j < 32; j++) {
            const int col = half + 2 * j;
            const float x0 = dr - (float)col * delta;
            const float x1 = dr - (float)(col + 1) * delta;
            xp[j] = pack_f16x2(expf(coeff * x0 * x0), expf(coeff * x1 * x1));
        }
    }
    cp_async_wait<0>();
    __syncthreads();

    const uint32_t aRowBase0 = (uint32_t)((wm * 32 + r16) * LDX + c8) * 2;
    const uint32_t aRowBase1 = (uint32_t)((wm * 32 + 16 + r16) * LDX + c8) * 2;
    const uint32_t bRowBase  = (uint32_t)(r16 * LDX + wn * 64 + c8) * 2;

    #pragma unroll 1
    for (int d = 0; d < NLAYER; d++) {
        // prefetch next layer's weights into the other buffer
        if (d + 1 < NLAYER) {
            const uint32_t* src = g_Whf + (d + 1) * MATU32;
            const uint32_t dst = sb + OFF_W + ((d + 1) & 1) * MATB;
            for (int i = t; i < 2176; i += THREADS)
                cp_async16(dst + i * 16, src + i * 4);
            cp_async_commit();
        }

        const uint32_t wb = sb + OFF_W + (d & 1) * MATB + bRowBase;

        float acc[2][8][4];
        #pragma unroll
        for (int mt = 0; mt < 2; mt++)
            #pragma unroll
            for (int nt = 0; nt < 8; nt++)
                #pragma unroll
                for (int q = 0; q < 4; q++) acc[mt][nt][q] = 0.f;

        // software-pipelined A and B fragments
        uint32_t a[2][4], an[2][4], bb0[4], bb1[4];
        ldsm_x4(a[0], sb + OFF_X + aRowBase0);
        ldsm_x4(a[1], sb + OFF_X + aRowBase1);
        ldsm_x4_t(bb0, wb);   // (kk=0, ng=0)

        #pragma unroll
        for (int kk = 0; kk < 8; kk++) {
            const uint32_t wk = wb + (uint32_t)(kk * 16 * LDX) * 2;
            if (kk < 7) {
                ldsm_x4(an[0], sb + OFF_X + aRowBase0 + (uint32_t)((kk + 1) * 16) * 2);
                ldsm_x4(an[1], sb + OFF_X + aRowBase1 + (uint32_t)((kk + 1) * 16) * 2);
            }
            #pragma unroll
            for (int ng = 0; ng < 4; ng++) {
                uint32_t* cur = ((ng & 1) == 0) ? bb0 : bb1;
                uint32_t* nxt = ((ng & 1) == 0) ? bb1 : bb0;
                if (ng < 3)
                    ldsm_x4_t(nxt, wk + (uint32_t)((ng + 1) * 16) * 2);
                else if (kk < 7)
                    ldsm_x4_t(nxt, wb + (uint32_t)((kk + 1) * 16 * LDX) * 2);
                mma_f16(acc[0][2*ng],   a[0], &cur[0]);
                mma_f16(acc[0][2*ng+1], a[0], &cur[2]);
                mma_f16(acc[1][2*ng],   a[1], &cur[0]);
                mma_f16(acc[1][2*ng+1], a[1], &cur[2]);
            }
            if (kk < 7) {
                #pragma unroll
                for (int q = 0; q < 4; q++) { a[0][q] = an[0][q]; a[1][q] = an[1][q]; }
            }
        }

        // X reads done -> release partner early; barrier hides under epilogue
        pair_bar(wm);

        // bias + relu
        const bool relu = ((d & 1) == 0);
        const float* bl_ = bias + d * KF;
        #pragma unroll
        for (int nt = 0; nt < 8; nt++) {
            const int c = wn * 64 + nt * 8 + tig * 2;
            const float b0 = bl_[c], b1 = bl_[c + 1];
            #pragma unroll
            for (int mt = 0; mt < 2; mt++) {
                acc[mt][nt][0] += b0; acc[mt][nt][1] += b1;
                acc[mt][nt][2] += b0; acc[mt][nt][3] += b1;
                if (relu) {
                    acc[mt][nt][0] = fmaxf(acc[mt][nt][0], 0.f);
                    acc[mt][nt][1] = fmaxf(acc[mt][nt][1], 0.f);
                    acc[mt][nt][2] = fmaxf(acc[mt][nt][2], 0.f);
                    acc[mt][nt][3] = fmaxf(acc[mt][nt][3], 0.f);
                }
            }
        }

        // KNN-mean (this warp's 32 rows = one cg group)
        if (d < 12 && (d & 3) == 1) {
            #pragma unroll
            for (int nt = 0; nt < 8; nt++) {
                float s0 = acc[0][nt][0] + acc[0][nt][2] + acc[1][nt][0] + acc[1][nt][2];
                float s1 = acc[0][nt][1] + acc[0][nt][3] + acc[1][nt][1] + acc[1][nt][3];
                #pragma unroll
                for (int m = 4; m <= 16; m <<= 1) {
                    s0 += __shfl_xor_sync(0xffffffffu, s0, m);
                    s1 += __shfl_xor_sync(0xffffffffu, s1, m);
                }
                s0 *= (1.0f / 32.0f);
                s1 *= (1.0f / 32.0f);
                #pragma unroll
                for (int mt = 0; mt < 2; mt++) {
                    acc[mt][nt][0] += s0; acc[mt][nt][2] += s0;
                    acc[mt][nt][1] += s1; acc[mt][nt][3] += s1;
                }
            }
        }

        if (d < 12) {
            // write activations back as fp16 pairs
            uint32_t* X = (uint32_t*)(smem + OFF_X);
            #pragma unroll
            for (int mt = 0; mt < 2; mt++) {
                const int r0 = 32 * wm + 16 * mt + grp;
                #pragma unroll
                for (int nt = 0; nt < 8; nt++) {
                    const int c = wn * 64 + nt * 8 + tig * 2;
                    X[(r0 * LDX + c) / 2]       = pack_f16x2(acc[mt][nt][0], acc[mt][nt][1]);
                    X[((r0 + 8) * LDX + c) / 2] = pack_f16x2(acc[mt][nt][2], acc[mt][nt][3]);
                }
            }
        } else {
            // G[b][col][n] += sum_rows F[row][col] * dv[row][n]
            float dvc[2][2][3];
            #pragma unroll
            for (int mt = 0; mt < 2; mt++) {
                const int r0 = 32 * wm + 16 * mt + grp;
                #pragma unroll
                for (int h = 0; h < 2; h++) {
                    dvc[mt][h][0] = dv[(r0 + 8*h) * 4 + 0];
                    dvc[mt][h][1] = dv[(r0 + 8*h) * 4 + 1];
                    dvc[mt][h][2] = dv[(r0 + 8*h) * 4 + 2];
                }
            }
            #pragma unroll
            for (int nt = 0; nt < 8; nt++) {
                float g0[3] = {0.f,0.f,0.f}, g1[3] = {0.f,0.f,0.f};
                #pragma unroll
                for (int mt = 0; mt < 2; mt++)
                    #pragma unroll
                    for (int n = 0; n < 3; n++) {
                        g0[n] += acc[mt][nt][0] * dvc[mt][0][n]
                               + acc[mt][nt][2] * dvc[mt][1][n];
                        g1[n] += acc[mt][nt][1] * dvc[mt][0][n]
                               + acc[mt][nt][3] * dvc[mt][1][n];
                    }
                #pragma unroll
                for (int m = 4; m <= 16; m <<= 1)
                    #pragma unroll
                    for (int n = 0; n < 3; n++) {
                        g0[n] += __shfl_xor_sync(0xffffffffu, g0[n], m);
                        g1[n] += __shfl_xor_sync(0xffffffffu, g1[n], m);
                    }
                if (grp == 0) {
                    const int c = wn * 64 + nt * 8 + tig * 2;
                    float* gp = g_G + (size_t)(b * KF + c) * 3;
                    atomicAdd(gp + 0, g0[0]);
                    atomicAdd(gp + 1, g0[1]);
                    atomicAdd(gp + 2, g0[2]);
                    atomicAdd(gp + 3, g1[0]);
                    atomicAdd(gp + 4, g1[1]);
                    atomicAdd(gp + 5, g1[2]);
                }
            }
        }

        cp_async_wait<0>();
        __syncthreads();   // X writes + W buffer visible CTA-wide
    }

    // S[b][n] += sum_rows dv[row][n]  (parallel: 3 warps, shuffle reduce)
    if (t < 96) {
        const int n = t >> 5;
        const int l = t & 31;
        float s = dv[l * 4 + n] + dv[(l + 32) * 4 + n]
                + dv[(l + 64) * 4 + n] + dv[(l + 96) * 4 + n];
        #pragma unroll
        for (int m = 16; m >= 1; m >>= 1)
            s += __shfl_xor_sync(0xffffffffu, s, m);
        if (l == 0) atomicAdd(&g_S[b * 3 + n], s);
    }
}

// ---------------- dx_recon = G @ dec_W2 + dec_b2 * S (split-K 8, atomic) ----------------
__global__ void dx_kernel(const float* __restrict__ dec_W2,
                          const float* __restrict__ dec_b2) {
    __shared__ float Gs[16 * 3];
    __shared__ float Ss[3];
    const int b     = blockIdx.x >> 5;
    const int chunk = (blockIdx.x >> 2) & 7;   // k chunk of 16
    const int oc    = blockIdx.x & 3;          // o chunk of 256
    const int o     = (oc << 8) + threadIdx.x;
    if (threadIdx.x < 48)
        Gs[threadIdx.x] = g_G[b * KF * 3 + chunk * 48 + threadIdx.x];
    if (threadIdx.x < 3) Ss[threadIdx.x] = g_S[b * 3 + threadIdx.x];
    __syncthreads();
    float d0 = 0.f, d1 = 0.f, d2 = 0.f;
    #pragma unroll
    for (int kk = 0; kk < 16; kk++) {
        const float w = dec_W2[(size_t)(chunk * 16 + kk) * NATOMS + o];
        d0 = fmaf(Gs[kk*3+0], w, d0);
        d1 = fmaf(Gs[kk*3+1], w, d1);
        d2 = fmaf(Gs[kk*3+2], w, d2);
    }
    if (chunk == 0) {
        const float bb = dec_b2[o];
        d0 += bb * Ss[0]; d1 += bb * Ss[1]; d2 += bb * Ss[2];
    }
    float* p = g_dx + (size_t)(b * NATOMS + o) * 3;
    atomicAdd(p + 0, d0);
    atomicAdd(p + 1, d1);
    atomicAdd(p + 2, d2);
}

// ---------------- cg_offset (32-atom chunks, grid = 16*32) ----------------
__global__ void cgoff_kernel(const float* __restrict__ assign_norm) {
    __shared__ float dxs[32 * 3];
    const int b  = blockIdx.x >> 5;
    const int oc = blockIdx.x & 31;
    const int j  = threadIdx.x;
    const int obase = oc * 32;
    if (threadIdx.x < 96)
        dxs[threadIdx.x] = g_dx[(size_t)(b * NATOMS + obase) * 3 + threadIdx.x];
    __syncthreads();
    float a0 = 0.f, a1 = 0.f, a2 = 0.f;
    #pragma unroll 4
    for (int oo = 0; oo < 32; oo++) {
        const float an = assign_norm[((size_t)b * NATOMS + obase + oo) * NCG + j];
        a0 = fmaf(an, dxs[oo*3+0], a0);
        a1 = fmaf(an, dxs[oo*3+1], a1);
        a2 = fmaf(an, dxs[oo*3+2], a2);
    }
    atomicAdd(&g_cgoff[(b * NCG + j) * 3 + 0], a0);
    atomicAdd(&g_cgoff[(b * NCG + j) * 3 + 1], a1);
    atomicAdd(&g_cgoff[(b * NCG + j) * 3 + 2], a2);
}

// ---------------- xyz_recon ----------------
__global__ void recon_kernel(const float* __restrict__ cg_xyz,
                             const int* __restrict__ assign_idx,
                             float* __restrict__ out) {
    const int i = blockIdx.x * blockDim.x + threadIdx.x;
    if (i >= BB * NATOMS) return;
    const int b = i >> 10;
    const int o = i & 1023;
    const int ai = assign_idx[o];
    const float* cx = cg_xyz + (size_t)(b * NCG + ai) * 3;
    const float* co = g_cgoff + (size_t)(b * NCG + ai) * 3;
    const float* dx = g_dx + (size_t)i * 3;
    float* po = out + (size_t)BB * NATOMS * NCG + (size_t)BB * NATOMS * 3 + (size_t)i * 3;
    po[0] = cx[0] - co[0] + dx[0];
    po[1] = cx[1] - co[1] + dx[1];
    po[2] = cx[2] - co[2] + dx[2];
}

// ---------------- launch ----------------
extern "C" void kernel_launch(void* const* d_in, const int* in_sizes, int n_in,
                              void* d_out, int out_size) {
    const float* soft_assign = (const float*)d_in[0];
    const float* xyz         = (const float*)d_in[1];
    const float* cg_xyz      = (const float*)d_in[2];
    const float* assign_norm = (const float*)d_in[3];
    const int*   assign_idx  = (const int*)d_in[4];
    const float* mlp_W1 = (const float*)d_in[5];
    const float* mlp_b1 = (const float*)d_in[6];
    const float* mlp_W2 = (const float*)d_in[7];
    const float* mlp_b2 = (const float*)d_in[8];
    const float* upd_W1 = (const float*)d_in[9];
    const float* upd_b1 = (const float*)d_in[10];
    const float* upd_W2 = (const float*)d_in[11];
    const float* upd_b2 = (const float*)d_in[12];
    const float* dec_W1 = (const float*)d_in[13];
    const float* dec_b1 = (const float*)d_in[14];
    const float* dec_W2 = (const float*)d_in[15];
    const float* dec_b2 = (const float*)d_in[16];

    float* out = (float*)d_out;

    static cudaStream_t s2 = nullptr, s3 = nullptr;
    static cudaEvent_t evFork = nullptr, evJoin = nullptr, evZero = nullptr;
    if (s2 == nullptr) {
        cudaStreamCreateWithFlags(&s2, cudaStreamNonBlocking);
        cudaStreamCreateWithFlags(&s3, cudaStreamNonBlocking);
        cudaEventCreateWithFlags(&evFork, cudaEventDisableTiming);
        cudaEventCreateWithFlags(&evJoin, cudaEventDisableTiming);
        cudaEventCreateWithFlags(&evZero, cudaEventDisableTiming);
    }

    // fork: passthrough copies (s2) + scratch zeroing (s3) overlap compute chain
    cudaEventRecord(evFork, 0);
    cudaStreamWaitEvent(s2, evFork, 0);
    cudaStreamWaitEvent(s3, evFork, 0);
    cudaMemcpyAsync(out, soft_assign, (size_t)BB * NATOMS * NCG * sizeof(float),
                    cudaMemcpyDeviceToDevice, s2);
    cudaMemcpyAsync(out + (size_t)BB * NATOMS * NCG, xyz,
                    (size_t)BB * NATOMS * 3 * sizeof(float),
                    cudaMemcpyDeviceToDevice, s2);
    cudaEventRecord(evJoin, s2);
    zero_kernel<<<32, 256, 0, s3>>>();
    cudaEventRecord(evZero, s3);

    convert_kernel<<<(NWQUAD + NLAYER * KF + 255) / 256, 256>>>(
        mlp_W1, mlp_b1, mlp_W2, mlp_b2,
        upd_W1, upd_b1, upd_W2, upd_b2, dec_W1, dec_b1);

    cudaStreamWaitEvent(0, evZero, 0);   // fused needs zeroed scratch
    cudaFuncSetAttribute(fused_kernel, cudaFuncAttributeMaxDynamicSharedMemorySize,
                         SMEM_TOTAL);
    fused_kernel<<<BB * NCG / 4, THREADS, SMEM_TOTAL>>>(cg_xyz);

    dx_kernel<<<BB * 32, 256>>>(dec_W2, dec_b2);
    cgoff_kernel<<<BB * 32, 256>>>(assign_norm);
    recon_kernel<<<BB * NATOMS / 128, 128>>>(cg_xyz, assign_idx, out);

    cudaStreamWaitEvent(0, evJoin, 0);
}